// round 1
// baseline (speedup 1.0000x reference)
#include <cuda_runtime.h>
#include <math.h>

// Scratch (device globals; no allocation allowed)
__device__ float g_PEX[32 * 256];        // pos_enc(j) @ W1[0:64]
__device__ float g_PEY[32 * 256];        // pos_enc(r) @ W1[64:128] + b1
__device__ float g_PEB[32 * 256];        // pos_enc(c) @ Wb1[32:96] + bb1
__device__ float g_XC [64 * 32 * 256];   // x-chunk @ W1[128:160]
__device__ float g_S  [64];              // row sums of x
__device__ float g_u  [64 * 256];        // u[b,h] = sum_i x[b,i]*h[b,i,h]
__device__ float g_out[64 * 1024];       // einsum output (pre-bias)

__device__ __forceinline__ float tanh_fast(float v) {
    float y;
    asm("tanh.approx.f32 %0, %1;" : "=f"(y) : "f"(v));
    return y;
}

// ---------------------------------------------------------------------------
// K1: positional-encoding projections, x-chunk projections, row sums
// blocks [0,32): PEX/PEY/PEB for position p=blk
// blocks [32,2080): XC for (b,j)
// blocks [2080,2144): S[b]
// ---------------------------------------------------------------------------
__global__ void k1_setup(const float* __restrict__ x,
                         const float* __restrict__ W1,
                         const float* __restrict__ b1,
                         const float* __restrict__ Wb1,
                         const float* __restrict__ bb1) {
    int blk = blockIdx.x;
    int t = threadIdx.x;

    if (blk < 32) {
        __shared__ float pe[64];
        if (t < 64) {
            int k = t >> 1;
            double invf = exp(-(double)(2 * k) / 64.0 * log(10000.0));
            float ang = (float)((double)blk * invf);
            pe[t] = (t & 1) ? cosf(ang) : sinf(ang);
        }
        __syncthreads();
        float ax = 0.f, ay = 0.f, ab = 0.f;
#pragma unroll
        for (int d = 0; d < 64; d++) {
            float p = pe[d];
            ax = fmaf(p, W1[d * 256 + t], ax);
            ay = fmaf(p, W1[(64 + d) * 256 + t], ay);
            ab = fmaf(p, Wb1[(32 + d) * 256 + t], ab);
        }
        g_PEX[blk * 256 + t] = ax;
        g_PEY[blk * 256 + t] = ay + b1[t];
        g_PEB[blk * 256 + t] = ab + bb1[t];
    } else if (blk < 32 + 2048) {
        int q = blk - 32;
        int b = q >> 5, j = q & 31;
        __shared__ float xs[32];
        if (t < 32) xs[t] = x[b * 1024 + j * 32 + t];
        __syncthreads();
        float acc = 0.f;
#pragma unroll
        for (int c = 0; c < 32; c++)
            acc = fmaf(xs[c], W1[(128 + c) * 256 + t], acc);
        g_XC[(b * 32 + j) * 256 + t] = acc;
    } else {
        int b = blk - 2080;
        __shared__ float red[256];
        float s = 0.f;
        for (int i = t; i < 1024; i += 256) s += x[b * 1024 + i];
        red[t] = s;
        __syncthreads();
        for (int off = 128; off > 0; off >>= 1) {
            if (t < off) red[t] += red[t + off];
            __syncthreads();
        }
        if (t == 0) g_S[b] = red[0];
    }
}

// ---------------------------------------------------------------------------
// K2: u[b,h] = sum_{r,j} x[b, r*32+j] * tanh(PEX[j,h] + XC[b,j,h] + PEY[r,h])
// grid 64*8 blocks: (b, h-chunk of 32). 256 threads: lane = h_local, warp = r-group.
// ---------------------------------------------------------------------------
__global__ void k2_u(const float* __restrict__ x) {
    int b = blockIdx.x >> 3;
    int hc = blockIdx.x & 7;
    int t = threadIdx.x;
    int hl = t & 31;
    int rg = t >> 5;          // warp id: covers r in [rg*4, rg*4+4)
    int h = hc * 32 + hl;

    __shared__ float xs[1024];
    for (int i = t; i < 1024; i += 256) xs[i] = x[b * 1024 + i];

    float A[32];
#pragma unroll
    for (int j = 0; j < 32; j++)
        A[j] = g_PEX[j * 256 + h] + g_XC[(b * 32 + j) * 256 + h];
    __syncthreads();

    float acc = 0.f;
#pragma unroll
    for (int rr = 0; rr < 4; rr++) {
        int r = rg * 4 + rr;
        float C = g_PEY[r * 256 + h];
        const float* xr = &xs[r * 32];
#pragma unroll
        for (int j = 0; j < 32; j++)
            acc = fmaf(xr[j], tanh_fast(A[j] + C), acc);
    }

    __shared__ float red[8][33];
    red[rg][hl] = acc;
    __syncthreads();
    if (t < 32) {
        float s = 0.f;
#pragma unroll
        for (int p = 0; p < 8; p++) s += red[p][t];
        g_u[b * 256 + hc * 32 + t] = s;
    }
}

// ---------------------------------------------------------------------------
// K3: out[b,o] = u[b,:] @ W2[:,o] + S[b]*b2[o]
// grid 64*4 blocks: (b, o-chunk of 256)
// ---------------------------------------------------------------------------
__global__ void k3_out(const float* __restrict__ W2,
                       const float* __restrict__ b2) {
    int b = blockIdx.x >> 2;
    int oc = blockIdx.x & 3;
    int t = threadIdx.x;
    int o = oc * 256 + t;

    __shared__ float us[256];
    us[t] = g_u[b * 256 + t];
    __syncthreads();

    float acc = g_S[b] * b2[o];
#pragma unroll 8
    for (int h = 0; h < 256; h++)
        acc = fmaf(us[h], W2[h * 1024 + o], acc);
    g_out[b * 1024 + o] = acc;
}

// ---------------------------------------------------------------------------
// K4: bias hypernetwork + final add. Block per b.
// For chunk c: hb = tanh(out[b,c*32:+32] @ Wb1[0:32] + PEB[c,:])
//              bias = hb @ Wb2 + bb2 ; y = out + bias
// ---------------------------------------------------------------------------
__global__ void k4_bias(const float* __restrict__ Wb1,
                        const float* __restrict__ Wb2,
                        const float* __restrict__ bb2,
                        float* __restrict__ y) {
    int b = blockIdx.x;
    int t = threadIdx.x;

    __shared__ float os[1024];
    __shared__ float hb[256];
    __shared__ float red[8][33];

    for (int i = t; i < 1024; i += 256) os[i] = g_out[b * 1024 + i];
    __syncthreads();

    int m = t & 31, p = t >> 5;
    for (int c = 0; c < 32; c++) {
        float a = g_PEB[c * 256 + t];
#pragma unroll
        for (int k = 0; k < 32; k++)
            a = fmaf(os[c * 32 + k], Wb1[k * 256 + t], a);
        hb[t] = tanh_fast(a);
        __syncthreads();

        float s = 0.f;
#pragma unroll
        for (int hh = 0; hh < 32; hh++)
            s = fmaf(hb[p * 32 + hh], Wb2[(p * 32 + hh) * 32 + m], s);
        red[p][m] = s;
        __syncthreads();

        if (t < 32) {
            float bias = bb2[t];
#pragma unroll
            for (int p2 = 0; p2 < 8; p2++) bias += red[p2][t];
            y[b * 1024 + c * 32 + t] = os[c * 32 + t] + bias;
        }
        __syncthreads();
    }
}

extern "C" void kernel_launch(void* const* d_in, const int* in_sizes, int n_in,
                              void* d_out, int out_size) {
    const float* x   = (const float*)d_in[0];
    // d_in[1] = output_size (int) — fixed at 1024 by the problem shapes
    const float* W1  = (const float*)d_in[2];
    const float* b1  = (const float*)d_in[3];
    const float* W2  = (const float*)d_in[4];
    const float* b2  = (const float*)d_in[5];
    const float* Wb1 = (const float*)d_in[6];
    const float* bb1 = (const float*)d_in[7];
    const float* Wb2 = (const float*)d_in[8];
    const float* bb2 = (const float*)d_in[9];
    float* y = (float*)d_out;

    k1_setup<<<2144, 256>>>(x, W1, b1, Wb1, bb1);
    k2_u<<<512, 256>>>(x);
    k3_out<<<256, 256>>>(W2, b2);
    k4_bias<<<64, 256>>>(Wb1, Wb2, bb2, y);
}

// round 2
// speedup vs baseline: 1.4071x; 1.4071x over previous
#include <cuda_runtime.h>
#include <math.h>

// Scratch (device globals; no allocation allowed)
__device__ float g_PEX[32 * 256];        // pos_enc(j) @ W1[0:64]
__device__ float g_PEY[32 * 256];        // pos_enc(r) @ W1[64:128] + b1
__device__ float g_PEB[32 * 256];        // pos_enc(c) @ Wb1[32:96] + bb1
__device__ float g_XC [64 * 32 * 256];   // x-chunk @ W1[128:160]
__device__ float g_S  [64];              // row sums of x
__device__ float g_u  [64 * 256];        // u[b,h] = sum_i x[b,i]*h[b,i,h]
__device__ float g_out[64 * 1024];       // einsum output (pre-bias)

__device__ __forceinline__ float tanh_fast(float v) {
    float y;
    asm("tanh.approx.f32 %0, %1;" : "=f"(y) : "f"(v));
    return y;
}

// ---------------------------------------------------------------------------
// K1: positional-encoding projections, x-chunk projections, row sums
// blocks [0,32): PEX/PEY/PEB for position p=blk
// blocks [32,2080): XC for (b,j)
// blocks [2080,2144): S[b]
// ---------------------------------------------------------------------------
__global__ void k1_setup(const float* __restrict__ x,
                         const float* __restrict__ W1,
                         const float* __restrict__ b1,
                         const float* __restrict__ Wb1,
                         const float* __restrict__ bb1) {
    int blk = blockIdx.x;
    int t = threadIdx.x;

    if (blk < 32) {
        __shared__ float pe[64];
        if (t < 64) {
            int k = t >> 1;
            double invf = exp(-(double)(2 * k) / 64.0 * log(10000.0));
            float ang = (float)((double)blk * invf);
            pe[t] = (t & 1) ? cosf(ang) : sinf(ang);
        }
        __syncthreads();
        float ax = 0.f, ay = 0.f, ab = 0.f;
#pragma unroll
        for (int d = 0; d < 64; d++) {
            float p = pe[d];
            ax = fmaf(p, W1[d * 256 + t], ax);
            ay = fmaf(p, W1[(64 + d) * 256 + t], ay);
            ab = fmaf(p, Wb1[(32 + d) * 256 + t], ab);
        }
        g_PEX[blk * 256 + t] = ax;
        g_PEY[blk * 256 + t] = ay + b1[t];
        g_PEB[blk * 256 + t] = ab + bb1[t];
    } else if (blk < 32 + 2048) {
        int q = blk - 32;
        int b = q >> 5, j = q & 31;
        __shared__ float xs[32];
        if (t < 32) xs[t] = x[b * 1024 + j * 32 + t];
        __syncthreads();
        float acc = 0.f;
#pragma unroll
        for (int c = 0; c < 32; c++)
            acc = fmaf(xs[c], W1[(128 + c) * 256 + t], acc);
        g_XC[(b * 32 + j) * 256 + t] = acc;
    } else {
        int b = blk - 2080;
        __shared__ float red[256];
        float s = 0.f;
        for (int i = t; i < 1024; i += 256) s += x[b * 1024 + i];
        red[t] = s;
        __syncthreads();
        for (int off = 128; off > 0; off >>= 1) {
            if (t < off) red[t] += red[t + off];
            __syncthreads();
        }
        if (t == 0) g_S[b] = red[0];
    }
}

// ---------------------------------------------------------------------------
// K2: u[b,h] = sum_{r,j} x[b, r*32+j] * tanh(PEX[j,h] + XC[b,j,h] + PEY[r,h])
// grid 64*8 blocks: (b, h-chunk of 32). 256 threads: lane = h_local, warp = r-group.
// ---------------------------------------------------------------------------
__global__ void k2_u(const float* __restrict__ x) {
    int b = blockIdx.x >> 3;
    int hc = blockIdx.x & 7;
    int t = threadIdx.x;
    int hl = t & 31;
    int rg = t >> 5;          // warp id: covers r in [rg*4, rg*4+4)
    int h = hc * 32 + hl;

    __shared__ float xs[1024];
    for (int i = t; i < 1024; i += 256) xs[i] = x[b * 1024 + i];

    float A[32];
#pragma unroll
    for (int j = 0; j < 32; j++)
        A[j] = g_PEX[j * 256 + h] + g_XC[(b * 32 + j) * 256 + h];
    __syncthreads();

    float acc = 0.f;
#pragma unroll
    for (int rr = 0; rr < 4; rr++) {
        int r = rg * 4 + rr;
        float C = g_PEY[r * 256 + h];
        const float* xr = &xs[r * 32];
#pragma unroll
        for (int j = 0; j < 32; j++)
            acc = fmaf(xr[j], tanh_fast(A[j] + C), acc);
    }

    __shared__ float red[8][33];
    red[rg][hl] = acc;
    __syncthreads();
    if (t < 32) {
        float s = 0.f;
#pragma unroll
        for (int p = 0; p < 8; p++) s += red[p][t];
        g_u[b * 256 + hc * 32 + t] = s;
    }
}

// ---------------------------------------------------------------------------
// K3: out[b,o] = u[b,:] @ W2[:,o] + S[b]*b2[o]
// grid 128 blocks: (b-group of 8) x (o-chunk of 64). 256 threads = 64 o-lanes
// x 4 h-groups. u held transposed in smem so one W2 load feeds 8 FMAs.
// ---------------------------------------------------------------------------
__global__ void k3_out(const float* __restrict__ W2,
                       const float* __restrict__ b2) {
    int bg = blockIdx.x >> 4;     // 0..7  (batch group of 8)
    int oc = blockIdx.x & 15;     // 0..15 (o chunk of 64)
    int t = threadIdx.x;
    int ol = t & 63;
    int hg = t >> 6;              // 0..3 (h group of 64)
    int o = oc * 64 + ol;

    __shared__ float us[256][8];  // [h][bb]
    __shared__ float Ss[8];
    for (int i = t; i < 256 * 8; i += 256) {
        int h = i >> 3, bb = i & 7;
        us[h][bb] = g_u[(bg * 8 + bb) * 256 + h];
    }
    if (t < 8) Ss[t] = g_S[bg * 8 + t];
    __syncthreads();

    float acc[8] = {0.f, 0.f, 0.f, 0.f, 0.f, 0.f, 0.f, 0.f};
#pragma unroll 8
    for (int hh = 0; hh < 64; hh++) {
        int h = hg * 64 + hh;
        float w = W2[h * 1024 + o];
#pragma unroll
        for (int bb = 0; bb < 8; bb++)
            acc[bb] = fmaf(us[h][bb], w, acc[bb]);
    }

    __shared__ float red[4][8][64];
#pragma unroll
    for (int bb = 0; bb < 8; bb++) red[hg][bb][ol] = acc[bb];
    __syncthreads();

#pragma unroll
    for (int pass = 0; pass < 2; pass++) {
        int bb = hg + pass * 4;
        float s = red[0][bb][ol] + red[1][bb][ol] + red[2][bb][ol] + red[3][bb][ol];
        s = fmaf(Ss[bb], b2[o], s);
        g_out[(bg * 8 + bb) * 1024 + o] = s;
    }
}

// ---------------------------------------------------------------------------
// K4: bias hypernetwork + final add. One block per (b, chunk c) -> 2048 blocks.
// hb = tanh(out[b,c*32:+32] @ Wb1[0:32] + PEB[c,:]); bias = hb @ Wb2 + bb2
// ---------------------------------------------------------------------------
__global__ void k4_bias(const float* __restrict__ Wb1,
                        const float* __restrict__ Wb2,
                        const float* __restrict__ bb2,
                        float* __restrict__ y) {
    int b = blockIdx.x >> 5;
    int c = blockIdx.x & 31;
    int t = threadIdx.x;

    __shared__ float os[32];
    __shared__ float hb[256];
    __shared__ float red[8][33];

    if (t < 32) os[t] = g_out[b * 1024 + c * 32 + t];
    __syncthreads();

    float a = g_PEB[c * 256 + t];
#pragma unroll
    for (int k = 0; k < 32; k++)
        a = fmaf(os[k], Wb1[k * 256 + t], a);
    hb[t] = tanh_fast(a);
    __syncthreads();

    int m = t & 31, p = t >> 5;
    float s = 0.f;
#pragma unroll
    for (int hh = 0; hh < 32; hh++)
        s = fmaf(hb[p * 32 + hh], Wb2[(p * 32 + hh) * 32 + m], s);
    red[p][m] = s;
    __syncthreads();

    if (t < 32) {
        float bias = bb2[t];
#pragma unroll
        for (int p2 = 0; p2 < 8; p2++) bias += red[p2][t];
        y[b * 1024 + c * 32 + t] = os[t] + bias;
    }
}

extern "C" void kernel_launch(void* const* d_in, const int* in_sizes, int n_in,
                              void* d_out, int out_size) {
    const float* x   = (const float*)d_in[0];
    // d_in[1] = output_size (int) — fixed at 1024 by the problem shapes
    const float* W1  = (const float*)d_in[2];
    const float* b1  = (const float*)d_in[3];
    const float* W2  = (const float*)d_in[4];
    const float* b2  = (const float*)d_in[5];
    const float* Wb1 = (const float*)d_in[6];
    const float* bb1 = (const float*)d_in[7];
    const float* Wb2 = (const float*)d_in[8];
    const float* bb2 = (const float*)d_in[9];
    float* y = (float*)d_out;

    k1_setup<<<2144, 256>>>(x, W1, b1, Wb1, bb1);
    k2_u<<<512, 256>>>(x);
    k3_out<<<128, 256>>>(W2, b2);
    k4_bias<<<2048, 256>>>(Wb1, Wb2, bb2, y);
}

// round 3
// speedup vs baseline: 1.5631x; 1.1109x over previous
#include <cuda_runtime.h>
#include <math.h>

// Scratch (device globals; no allocation allowed)
__device__ float g_PEX[32 * 256];        // pos_enc(j) @ W1[0:64]
__device__ float g_PEY[32 * 256];        // pos_enc(r) @ W1[64:128] + b1
__device__ float g_PEB[32 * 256];        // pos_enc(c) @ Wb1[32:96] + bb1
__device__ float g_XC [64 * 32 * 256];   // x-chunk @ W1[128:160]
__device__ float g_S  [64];              // row sums of x
__device__ float g_u  [64 * 256];        // u[b,h] = sum_i x[b,i]*h[b,i,h]
__device__ float g_out[64 * 1024];       // einsum output (pre-bias)

__device__ __forceinline__ float tanh_fast(float v) {
    float y;
    asm("tanh.approx.f32 %0, %1;" : "=f"(y) : "f"(v));
    return y;
}

// ---------------------------------------------------------------------------
// K1: positional-encoding projections, x-chunk projections, row sums
// ---------------------------------------------------------------------------
__global__ void k1_setup(const float* __restrict__ x,
                         const float* __restrict__ W1,
                         const float* __restrict__ b1,
                         const float* __restrict__ Wb1,
                         const float* __restrict__ bb1) {
    int blk = blockIdx.x;
    int t = threadIdx.x;

    if (blk < 32) {
        __shared__ float pe[64];
        if (t < 64) {
            int k = t >> 1;
            double invf = exp(-(double)(2 * k) / 64.0 * log(10000.0));
            float ang = (float)((double)blk * invf);
            pe[t] = (t & 1) ? cosf(ang) : sinf(ang);
        }
        __syncthreads();
        float ax = 0.f, ay = 0.f, ab = 0.f;
#pragma unroll
        for (int d = 0; d < 64; d++) {
            float p = pe[d];
            ax = fmaf(p, W1[d * 256 + t], ax);
            ay = fmaf(p, W1[(64 + d) * 256 + t], ay);
            ab = fmaf(p, Wb1[(32 + d) * 256 + t], ab);
        }
        g_PEX[blk * 256 + t] = ax;
        g_PEY[blk * 256 + t] = ay + b1[t];
        g_PEB[blk * 256 + t] = ab + bb1[t];
    } else if (blk < 32 + 2048) {
        int q = blk - 32;
        int b = q >> 5, j = q & 31;
        __shared__ float xs[32];
        if (t < 32) xs[t] = x[b * 1024 + j * 32 + t];
        __syncthreads();
        float acc = 0.f;
#pragma unroll
        for (int c = 0; c < 32; c++)
            acc = fmaf(xs[c], W1[(128 + c) * 256 + t], acc);
        g_XC[(b * 32 + j) * 256 + t] = acc;
    } else {
        int b = blk - 2080;
        __shared__ float red[256];
        float s = 0.f;
        for (int i = t; i < 1024; i += 256) s += x[b * 1024 + i];
        red[t] = s;
        __syncthreads();
        for (int off = 128; off > 0; off >>= 1) {
            if (t < off) red[t] += red[t + off];
            __syncthreads();
        }
        if (t == 0) g_S[b] = red[0];
    }
}

// ---------------------------------------------------------------------------
// K2: u[b,h] = sum_{r,j} x[b, r*32+j] * tanh(PEX[j,h] + XC[b,j,h] + PEY[r,h])
// ---------------------------------------------------------------------------
__global__ void k2_u(const float* __restrict__ x) {
    int b = blockIdx.x >> 3;
    int hc = blockIdx.x & 7;
    int t = threadIdx.x;
    int hl = t & 31;
    int rg = t >> 5;
    int h = hc * 32 + hl;

    __shared__ float xs[1024];
    for (int i = t; i < 1024; i += 256) xs[i] = x[b * 1024 + i];

    float A[32];
#pragma unroll
    for (int j = 0; j < 32; j++)
        A[j] = g_PEX[j * 256 + h] + g_XC[(b * 32 + j) * 256 + h];
    __syncthreads();

    float acc = 0.f;
#pragma unroll
    for (int rr = 0; rr < 4; rr++) {
        int r = rg * 4 + rr;
        float C = g_PEY[r * 256 + h];
        const float* xr = &xs[r * 32];
#pragma unroll
        for (int j = 0; j < 32; j++)
            acc = fmaf(xr[j], tanh_fast(A[j] + C), acc);
    }

    __shared__ float red[8][33];
    red[rg][hl] = acc;
    __syncthreads();
    if (t < 32) {
        float s = 0.f;
#pragma unroll
        for (int p = 0; p < 8; p++) s += red[p][t];
        g_u[b * 256 + hc * 32 + t] = s;
    }
}

// ---------------------------------------------------------------------------
// K3: out[b,o] = u[b,:] @ W2[:,o] + S[b]*b2[o]
// ---------------------------------------------------------------------------
__global__ void k3_out(const float* __restrict__ W2,
                       const float* __restrict__ b2) {
    int bg = blockIdx.x >> 4;
    int oc = blockIdx.x & 15;
    int t = threadIdx.x;
    int ol = t & 63;
    int hg = t >> 6;
    int o = oc * 64 + ol;

    __shared__ float us[256][8];
    __shared__ float Ss[8];
    for (int i = t; i < 256 * 8; i += 256) {
        int h = i >> 3, bb = i & 7;
        us[h][bb] = g_u[(bg * 8 + bb) * 256 + h];
    }
    if (t < 8) Ss[t] = g_S[bg * 8 + t];
    __syncthreads();

    float acc[8] = {0.f, 0.f, 0.f, 0.f, 0.f, 0.f, 0.f, 0.f};
#pragma unroll 8
    for (int hh = 0; hh < 64; hh++) {
        int h = hg * 64 + hh;
        float w = W2[h * 1024 + o];
#pragma unroll
        for (int bb = 0; bb < 8; bb++)
            acc[bb] = fmaf(us[h][bb], w, acc[bb]);
    }

    __shared__ float red[4][8][64];
#pragma unroll
    for (int bb = 0; bb < 8; bb++) red[hg][bb][ol] = acc[bb];
    __syncthreads();

#pragma unroll
    for (int pass = 0; pass < 2; pass++) {
        int bb = hg + pass * 4;
        float s = red[0][bb][ol] + red[1][bb][ol] + red[2][bb][ol] + red[3][bb][ol];
        s = fmaf(Ss[bb], b2[o], s);
        g_out[(bg * 8 + bb) * 1024 + o] = s;
    }
}

// ---------------------------------------------------------------------------
// K4: bias hypernetwork + final add, register-resident weights.
// Block = 8 rows (rows = (b, c0..c0+7)), 256 blocks x 256 threads.
// Layer1: thread t holds Wb1[:,t] in 32 regs; os via float4 smem broadcast.
// Layer2: thread (hg,m) holds Wb2[hg*32..+32, m] in 32 regs; H via float4
// smem broadcast; 8-way partial reduction in smem.
// ---------------------------------------------------------------------------
__global__ void __launch_bounds__(256) k4_bias(
        const float* __restrict__ Wb1,
        const float* __restrict__ Wb2,
        const float* __restrict__ bb2,
        float* __restrict__ y) {
    int blk = blockIdx.x;           // 0..255
    int b = blk >> 2;               // 0..63
    int c0 = (blk & 3) * 8;         // chunk base
    int t = threadIdx.x;

    __shared__ float os[8][32];     // out chunk values for 8 rows
    __shared__ float H[8][256];     // tanh hidden
    __shared__ float red[8][8][32]; // [hg][r][m]

    // load os: thread t -> (r = t>>5, k = t&31)
    os[t >> 5][t & 31] = g_out[b * 1024 + (c0 + (t >> 5)) * 32 + (t & 31)];

    // Wb1 column t (coalesced), reused for all 8 rows
    float w1[32];
#pragma unroll
    for (int k = 0; k < 32; k++) w1[k] = Wb1[k * 256 + t];

    // Wb2 slice (coalesced across m lanes), reused for all 8 rows
    int hg = t >> 5, m = t & 31;
    float w2[32];
#pragma unroll
    for (int hh = 0; hh < 32; hh++) w2[hh] = Wb2[(hg * 32 + hh) * 32 + m];

    __syncthreads();

    // Layer 1: H[r][t] = tanh(PEB[c0+r][t] + os[r,:] . w1)
#pragma unroll
    for (int r = 0; r < 8; r++) {
        float a = g_PEB[(c0 + r) * 256 + t];
        const float4* o4 = (const float4*)os[r];
#pragma unroll
        for (int q = 0; q < 8; q++) {
            float4 o = o4[q];
            a = fmaf(o.x, w1[4 * q + 0], a);
            a = fmaf(o.y, w1[4 * q + 1], a);
            a = fmaf(o.z, w1[4 * q + 2], a);
            a = fmaf(o.w, w1[4 * q + 3], a);
        }
        H[r][t] = tanh_fast(a);
    }
    __syncthreads();

    // Layer 2 partials: s[r] = H[r][hg*32..+32] . w2
    float s[8];
#pragma unroll
    for (int r = 0; r < 8; r++) s[r] = 0.f;
#pragma unroll
    for (int r = 0; r < 8; r++) {
        const float4* h4 = (const float4*)&H[r][hg * 32];
#pragma unroll
        for (int q = 0; q < 8; q++) {
            float4 hv = h4[q];
            s[r] = fmaf(hv.x, w2[4 * q + 0], s[r]);
            s[r] = fmaf(hv.y, w2[4 * q + 1], s[r]);
            s[r] = fmaf(hv.z, w2[4 * q + 2], s[r]);
            s[r] = fmaf(hv.w, w2[4 * q + 3], s[r]);
        }
    }
#pragma unroll
    for (int r = 0; r < 8; r++) red[hg][r][m] = s[r];
    __syncthreads();

    // Final: thread t -> (r = t>>5, m = t&31)
    {
        int r = t >> 5, mm = t & 31;
        float bias = bb2[mm];
#pragma unroll
        for (int p = 0; p < 8; p++) bias += red[p][r][mm];
        y[b * 1024 + (c0 + r) * 32 + mm] = os[r][mm] + bias;
    }
}

extern "C" void kernel_launch(void* const* d_in, const int* in_sizes, int n_in,
                              void* d_out, int out_size) {
    const float* x   = (const float*)d_in[0];
    // d_in[1] = output_size (int) — fixed at 1024 by the problem shapes
    const float* W1  = (const float*)d_in[2];
    const float* b1  = (const float*)d_in[3];
    const float* W2  = (const float*)d_in[4];
    const float* b2  = (const float*)d_in[5];
    const float* Wb1 = (const float*)d_in[6];
    const float* bb1 = (const float*)d_in[7];
    const float* Wb2 = (const float*)d_in[8];
    const float* bb2 = (const float*)d_in[9];
    float* y = (float*)d_out;

    k1_setup<<<2144, 256>>>(x, W1, b1, Wb1, bb1);
    k2_u<<<512, 256>>>(x);
    k3_out<<<128, 256>>>(W2, b2);
    k4_bias<<<256, 256>>>(Wb1, Wb2, bb2, y);
}